// round 3
// baseline (speedup 1.0000x reference)
#include <cuda_runtime.h>

#define S_LEN 1024
#define NP 513
#define PSTR 516
#define OUT_ELEMS 4194304
#define NROWS 65536

__device__ float g_P[(size_t)NROWS * PSTR];   // P[row,p] = q[row]·Wk[p]
__device__ float g_C[(size_t)NROWS * PSTR];   // shifted weights c[row,m]

// ---------------------------------------------------------------------------
// Kernel A: P = Q @ Wk^T, 128x128 tiles, 8x8 accum, full-K resident
// ---------------------------------------------------------------------------
__global__ void __launch_bounds__(256) kernA(const float* __restrict__ q,
                                             const float* __restrict__ Wk) {
    const int r0 = blockIdx.x * 128;
    const int p0 = blockIdx.y * 128;
    const int i0 = r0 & (S_LEN - 1);
    if (p0 + 127 < 385 - i0) return;   // tile entirely below min needed p
    extern __shared__ float dsmA[];
    float (*sQT)[132] = (float(*)[132])(dsmA);          // [d][r]
    float (*sWT)[132] = (float(*)[132])(dsmA + 8448);   // [d][p-p0]
    const int tid = threadIdx.x;
    #pragma unroll
    for (int l = 0; l < 8; ++l) {
        int e = tid + l * 256;
        int r = e & 127, c4 = (e >> 7) << 2;
        float4 vv = *(const float4*)(q + (size_t)(r0 + r) * 64 + c4);
        sQT[c4+0][r]=vv.x; sQT[c4+1][r]=vv.y; sQT[c4+2][r]=vv.z; sQT[c4+3][r]=vv.w;
    }
    #pragma unroll
    for (int l = 0; l < 8; ++l) {
        int e = tid + l * 256;
        int r = e & 127, c4 = (e >> 7) << 2;
        int p = p0 + r;
        float4 vv = make_float4(0.f,0.f,0.f,0.f);
        if (p < NP) vv = *(const float4*)(Wk + (size_t)p * 64 + c4);
        sWT[c4+0][r]=vv.x; sWT[c4+1][r]=vv.y; sWT[c4+2][r]=vv.z; sWT[c4+3][r]=vv.w;
    }
    __syncthreads();
    const int tx = tid & 15, ty = tid >> 4;
    float acc[8][8] = {};
    #pragma unroll 8
    for (int d = 0; d < 64; ++d) {
        float a[8], b[8];
        *(float4*)&a[0] = *(const float4*)&sQT[d][4*ty];
        *(float4*)&a[4] = *(const float4*)&sQT[d][4*ty + 64];
        *(float4*)&b[0] = *(const float4*)&sWT[d][4*tx];
        *(float4*)&b[4] = *(const float4*)&sWT[d][4*tx + 64];
        #pragma unroll
        for (int ri = 0; ri < 8; ++ri)
            #pragma unroll
            for (int ci = 0; ci < 8; ++ci)
                acc[ri][ci] += a[ri] * b[ci];
    }
    #pragma unroll
    for (int rs = 0; rs < 8; ++rs) {
        const int r = r0 + ((rs < 4) ? 4*ty + rs : 64 + 4*ty + rs - 4);
        const size_t row = (size_t)r * PSTR;
        const int c0 = p0 + 4*tx;
        if (c0 <= 512)
            *(float4*)(g_P + row + c0) = make_float4(acc[rs][0],acc[rs][1],acc[rs][2],acc[rs][3]);
        const int c1 = p0 + 64 + 4*tx;
        if (c1 <= 512)
            *(float4*)(g_P + row + c1) = make_float4(acc[rs][4],acc[rs][5],acc[rs][6],acc[rs][7]);
    }
}

// ---------------------------------------------------------------------------
// Fused B+C: 128-row i-blocks, 64-wide j-tiles, 8x4 accum, single-exp flash.
// ---------------------------------------------------------------------------
__global__ void __launch_bounds__(256) kernBC(const float* __restrict__ q,
                                              const float* __restrict__ kmat,
                                              const float* __restrict__ v,
                                              float* __restrict__ wbuf,
                                              float* __restrict__ outp) {
    extern __shared__ float dsm[];
    float (*sQT)[132] = (float(*)[132])(dsm);             // [d][r] 64x132
    float (*sKT)[68]  = (float(*)[68])(dsm + 8448);       // [d][j] 64x68
    float (*sV)[68]   = (float(*)[68])(dsm + 12800);      // [j][d] 64x68
    float (*sET)[132] = (float(*)[132])(dsm + 17152);     // [j][r] 64x132
    float *sMh  = dsm + 25600;   // [16][128]
    float *sM   = dsm + 27648;
    float *sS   = dsm + 27776;
    float *sCs  = dsm + 27904;
    float *sInv = dsm + 28032;
    float *sFac = dsm + 28160;

    const int bh = blockIdx.y;
    const int ibb = 7 - (int)blockIdx.x;     // heavy blocks first
    const int i0 = ibb * 128;
    const int rowbase = bh * S_LEN + i0;
    const int tid = threadIdx.x;
    const int tx = tid & 15, ty = tid >> 4;

    #pragma unroll
    for (int l = 0; l < 8; ++l) {
        int e = tid + l * 256;
        int r = e & 127, c4 = (e >> 7) << 2;
        float4 vv = *(const float4*)(q + (size_t)(rowbase + r) * 64 + c4);
        sQT[c4+0][r]=vv.x; sQT[c4+1][r]=vv.y; sQT[c4+2][r]=vv.z; sQT[c4+3][r]=vv.w;
    }
    if (tid < 128) { sM[tid] = -1e30f; sS[tid] = 0.f; sCs[tid] = 0.f; }

    float accO[8][4] = {};
    const int jbmax = 2 * ibb + 1;

    for (int jb = 0; jb <= jbmax; ++jb) {
        const int j0 = jb * 64;
        __syncthreads();
        #pragma unroll
        for (int l = 0; l < 4; ++l) {
            int e = tid + l * 256;
            int r = e & 63, c4 = (e >> 6) << 2;
            float4 vv = *(const float4*)(kmat + (size_t)(bh*S_LEN + j0 + r)*64 + c4);
            sKT[c4+0][r]=vv.x; sKT[c4+1][r]=vv.y; sKT[c4+2][r]=vv.z; sKT[c4+3][r]=vv.w;
        }
        #pragma unroll
        for (int l = 0; l < 4; ++l) {
            int e = tid + l * 256;
            int r = e >> 4, c4 = (e & 15) << 2;
            *(float4*)&sV[r][c4] = *(const float4*)(v + (size_t)(bh*S_LEN + j0 + r)*64 + c4);
        }
        __syncthreads();

        float accQ[8][4] = {};
        #pragma unroll 8
        for (int d = 0; d < 64; ++d) {
            float a[8], b[4];
            *(float4*)&a[0] = *(const float4*)&sQT[d][4*ty];
            *(float4*)&a[4] = *(const float4*)&sQT[d][4*ty + 64];
            *(float4*)&b[0] = *(const float4*)&sKT[d][4*tx];
            #pragma unroll
            for (int ri = 0; ri < 8; ++ri)
                #pragma unroll
                for (int ci = 0; ci < 4; ++ci)
                    accQ[ri][ci] += a[ri] * b[ci];
        }

        // bias + mask + online stats + exp (in place into accQ)
        #pragma unroll
        for (int rs = 0; rs < 8; ++rs) {
            const int rloc = (rs < 4) ? 4*ty + rs : 64 + 4*ty + rs - 4;
            const int i = i0 + rloc;
            const size_t prow = (size_t)(rowbase + rloc) * PSTR;
            #pragma unroll
            for (int ci = 0; ci < 4; ++ci) {
                const int j = j0 + 4*tx + ci;
                int p = j - i + 512; if (p < 0) p = 0;
                accQ[rs][ci] += g_P[prow + p];
                if (j > i) accQ[rs][ci] = -1e30f;
            }
            float mx = fmaxf(fmaxf(accQ[rs][0], accQ[rs][1]), fmaxf(accQ[rs][2], accQ[rs][3]));
            #pragma unroll
            for (int off = 8; off >= 1; off >>= 1)
                mx = fmaxf(mx, __shfl_xor_sync(0xffffffffu, mx, off));
            const float oldm = sM[rloc];
            const float newm = fmaxf(oldm, mx);
            const float cfr = __expf(oldm - newm);
            #pragma unroll
            for (int ci = 0; ci < 4; ++ci) accQ[rs][ci] = __expf(accQ[rs][ci] - newm);
            float se = accQ[rs][0] + accQ[rs][1] + accQ[rs][2] + accQ[rs][3];
            #pragma unroll
            for (int off = 8; off >= 1; off >>= 1)
                se += __shfl_xor_sync(0xffffffffu, se, off);
            if (tx == 0) { sS[rloc] = sS[rloc]*cfr + se; sM[rloc] = newm; sMh[jb*128 + rloc] = newm; }
            #pragma unroll
            for (int ci = 0; ci < 4; ++ci) accO[rs][ci] *= cfr;
        }

        // E -> wbuf (raw) and sET transposed (float4 along r: conflict-light)
        #pragma unroll
        for (int g = 0; g < 2; ++g) {
            const int rbase = 4*ty + g*64;
            #pragma unroll
            for (int ci = 0; ci < 4; ++ci)
                *(float4*)&sET[4*tx + ci][rbase] =
                    make_float4(accQ[g*4+0][ci], accQ[g*4+1][ci], accQ[g*4+2][ci], accQ[g*4+3][ci]);
            #pragma unroll
            for (int rr = 0; rr < 4; ++rr)
                *(float4*)(wbuf + (size_t)(rowbase + rbase + rr)*S_LEN + j0 + 4*tx)
                    = make_float4(accQ[g*4+rr][0], accQ[g*4+rr][1], accQ[g*4+rr][2], accQ[g*4+rr][3]);
        }
        __syncthreads();

        // accO += E @ V
        #pragma unroll 8
        for (int j = 0; j < 64; ++j) {
            float a[8], b[4];
            *(float4*)&a[0] = *(const float4*)&sET[j][4*ty];
            *(float4*)&a[4] = *(const float4*)&sET[j][4*ty + 64];
            *(float4*)&b[0] = *(const float4*)&sV[j][4*tx];
            #pragma unroll
            for (int ri = 0; ri < 8; ++ri)
                #pragma unroll
                for (int ci = 0; ci < 4; ++ci)
                    accO[ri][ci] += a[ri] * b[ci];
        }
    }

    __syncthreads();
    if (tid < 128) sInv[tid] = 1.0f / sS[tid];
    __syncthreads();

    #pragma unroll
    for (int rs = 0; rs < 8; ++rs) {
        const int rloc = (rs < 4) ? 4*ty + rs : 64 + 4*ty + rs - 4;
        const float inv = sInv[rloc];
        *(float4*)(outp + (size_t)(rowbase + rloc)*64 + 4*tx)
            = make_float4(accO[rs][0]*inv, accO[rs][1]*inv, accO[rs][2]*inv, accO[rs][3]*inv);
    }

    // pass2: finalize weights + scatter shifted weights into g_C
    for (int jb = 0; jb < 16; ++jb) {
        const int j0 = jb * 64;
        if (jb > jbmax) {
            const float4 z = make_float4(0.f,0.f,0.f,0.f);
            #pragma unroll
            for (int l = 0; l < 8; ++l) {
                int e = tid + l * 256;
                int r = e >> 4, c4 = (e & 15) << 2;
                *(float4*)(wbuf + (size_t)(rowbase + r)*S_LEN + j0 + c4) = z;
            }
            continue;
        }
        __syncthreads();
        if (tid < 128) sFac[tid] = __expf(sMh[jb*128 + tid] - sM[tid]) * sInv[tid];
        __syncthreads();
        #pragma unroll
        for (int l = 0; l < 8; ++l) {
            int e = tid + l * 256;
            int r = e >> 4, c4 = (e & 15) << 2;
            size_t addr = (size_t)(rowbase + r)*S_LEN + j0 + c4;
            float4 w = *(float4*)(wbuf + addr);
            const float f = sFac[r];
            w.x *= f; w.y *= f; w.z *= f; w.w *= f;
            *(float4*)(wbuf + addr) = w;
            const int i = i0 + r;
            const size_t crow = (size_t)(rowbase + r) * PSTR;
            const float wv[4] = {w.x, w.y, w.z, w.w};
            #pragma unroll
            for (int t = 0; t < 4; ++t) {
                int mm = i - (j0 + c4 + t);
                if (mm >= 0) {
                    if (mm < 512) g_C[crow + mm] = wv[t];
                    else          atomicAdd(&sCs[r], wv[t]);
                }
            }
        }
    }
    __syncthreads();
    if (tid < 128) g_C[(size_t)(rowbase + tid)*PSTR + 512] = sCs[tid];
    if (i0 < 512) {   // zero-fill never-written slots (m in (i,512))
        for (int idx = tid; idx < 128*512; idx += 256) {
            int r = idx >> 9, mm = idx & 511;
            if (mm > i0 + r) g_C[(size_t)(rowbase + r)*PSTR + mm] = 0.f;
        }
    }
}

// ---------------------------------------------------------------------------
// Kernel D: out += C @ Wv_rev, 256x64 tiles, 8x8 accum, K chunks of 64,
// truncated at m <= i0+255 (causal zeros above).
// ---------------------------------------------------------------------------
__global__ void __launch_bounds__(256) kernD(const float* __restrict__ Wv,
                                             float* __restrict__ outp) {
    extern __shared__ float dsmD[];
    float (*sCT)[260] = (float(*)[260])(dsmD);            // [m][r] 64x260
    float (*sB)[68]   = (float(*)[68])(dsmD + 16640);     // [m][d] 64x68
    const int r0 = blockIdx.x * 256;
    const int i0 = r0 & (S_LEN - 1);
    const int mEnd = min(NP, i0 + 256);
    const int tid = threadIdx.x;
    const int tx = tid & 7, ty = tid >> 3;   // tx: 8 col groups, ty: 32 row groups
    float acc[8][8] = {};

    for (int m0 = 0; m0 < mEnd; m0 += 64) {
        __syncthreads();
        #pragma unroll
        for (int l = 0; l < 16; ++l) {
            int e = tid + l * 256;
            int r = e & 255, c4 = (e >> 8) << 2;
            int mb = m0 + c4;
            float4 vv = make_float4(0.f,0.f,0.f,0.f);
            if (mb + 3 <= 512)
                vv = *(const float4*)(g_C + (size_t)(r0 + r)*PSTR + mb);
            else if (mb <= 512)
                vv.x = g_C[(size_t)(r0 + r)*PSTR + 512];
            sCT[c4+0][r]=vv.x; sCT[c4+1][r]=vv.y; sCT[c4+2][r]=vv.z; sCT[c4+3][r]=vv.w;
        }
        #pragma unroll
        for (int l = 0; l < 4; ++l) {
            int e = tid + l * 256;
            int mm = e >> 4, c4 = (e & 15) << 2;
            int m = m0 + mm;
            float4 vv = make_float4(0.f,0.f,0.f,0.f);
            if (m < NP) vv = *(const float4*)(Wv + (size_t)(512 - m)*64 + c4);
            *(float4*)&sB[mm][c4] = vv;
        }
        __syncthreads();
        #pragma unroll 8
        for (int m = 0; m < 64; ++m) {
            float a[8], b[8];
            *(float4*)&a[0] = *(const float4*)&sCT[m][4*ty];
            *(float4*)&a[4] = *(const float4*)&sCT[m][4*ty + 128];
            *(float4*)&b[0] = *(const float4*)&sB[m][4*tx];
            *(float4*)&b[4] = *(const float4*)&sB[m][4*tx + 32];
            #pragma unroll
            for (int ri = 0; ri < 8; ++ri)
                #pragma unroll
                for (int ci = 0; ci < 8; ++ci)
                    acc[ri][ci] += a[ri] * b[ci];
        }
    }
    #pragma unroll
    for (int rs = 0; rs < 8; ++rs) {
        const int r = r0 + ((rs < 4) ? 4*ty + rs : 128 + 4*ty + rs - 4);
        #pragma unroll
        for (int g = 0; g < 2; ++g) {
            size_t a = (size_t)r * 64 + 4*tx + g*32;
            float4 o = *(float4*)(outp + a);
            o.x += acc[rs][g*4+0]; o.y += acc[rs][g*4+1];
            o.z += acc[rs][g*4+2]; o.w += acc[rs][g*4+3];
            *(float4*)(outp + a) = o;
        }
    }
}

// ---------------------------------------------------------------------------
extern "C" void kernel_launch(void* const* d_in, const int* in_sizes, int n_in,
                              void* d_out, int out_size) {
    const float* q  = (const float*)d_in[0];
    const float* k  = (const float*)d_in[1];
    const float* v  = (const float*)d_in[2];
    const float* Wk = (const float*)d_in[3];
    const float* Wv = (const float*)d_in[4];

    float* outp = (float*)d_out;            // (B,H,S,D)
    float* wbuf = outp + OUT_ELEMS;         // (B,H,S,S) weights

    static bool attrs_set = false;
    if (!attrs_set) {
        cudaFuncSetAttribute(kernA,  cudaFuncAttributeMaxDynamicSharedMemorySize, 67584);
        cudaFuncSetAttribute(kernBC, cudaFuncAttributeMaxDynamicSharedMemorySize, 113152);
        cudaFuncSetAttribute(kernD,  cudaFuncAttributeMaxDynamicSharedMemorySize, 83968);
        attrs_set = true;
    }
    kernA<<<dim3(512, 5), 256, 67584>>>(q, Wk);
    kernBC<<<dim3(8, 64), 256, 113152>>>(q, k, v, wbuf, outp);
    kernD<<<dim3(256), 256, 83968>>>(Wv, outp);
}

// round 4
// speedup vs baseline: 1.0908x; 1.0908x over previous
#include <cuda_runtime.h>

#define S_LEN 1024
#define NP 513
#define PSTR 516
#define OUT_ELEMS 4194304
#define NROWS 65536

__device__ float g_P[(size_t)NROWS * PSTR];   // P[row,p] = q[row]·Wk[p]
__device__ float g_C[(size_t)NROWS * PSTR];   // shifted weights c[row,m]

// ---------------------------------------------------------------------------
// Kernel A: P = Q @ Wk^T, 128x128 tiles, 8x8 accum, full-K resident
// ---------------------------------------------------------------------------
__global__ void __launch_bounds__(256) kernA(const float* __restrict__ q,
                                             const float* __restrict__ Wk) {
    const int r0 = blockIdx.x * 128;
    const int p0 = blockIdx.y * 128;
    const int i0 = r0 & (S_LEN - 1);
    if (p0 + 127 < 385 - i0) return;   // tile entirely below min needed p
    extern __shared__ float dsmA[];
    float (*sQT)[132] = (float(*)[132])(dsmA);          // [d][r]
    float (*sWT)[132] = (float(*)[132])(dsmA + 8448);   // [d][p-p0]
    const int tid = threadIdx.x;
    #pragma unroll
    for (int l = 0; l < 8; ++l) {
        int e = tid + l * 256;
        int r = e & 127, c4 = (e >> 7) << 2;
        float4 vv = *(const float4*)(q + (size_t)(r0 + r) * 64 + c4);
        sQT[c4+0][r]=vv.x; sQT[c4+1][r]=vv.y; sQT[c4+2][r]=vv.z; sQT[c4+3][r]=vv.w;
    }
    #pragma unroll
    for (int l = 0; l < 8; ++l) {
        int e = tid + l * 256;
        int r = e & 127, c4 = (e >> 7) << 2;
        int p = p0 + r;
        float4 vv = make_float4(0.f,0.f,0.f,0.f);
        if (p < NP) vv = *(const float4*)(Wk + (size_t)p * 64 + c4);
        sWT[c4+0][r]=vv.x; sWT[c4+1][r]=vv.y; sWT[c4+2][r]=vv.z; sWT[c4+3][r]=vv.w;
    }
    __syncthreads();
    const int tx = tid & 15, ty = tid >> 4;
    float acc[8][8] = {};
    #pragma unroll 8
    for (int d = 0; d < 64; ++d) {
        float a[8], b[8];
        *(float4*)&a[0] = *(const float4*)&sQT[d][4*ty];
        *(float4*)&a[4] = *(const float4*)&sQT[d][4*ty + 64];
        *(float4*)&b[0] = *(const float4*)&sWT[d][4*tx];
        *(float4*)&b[4] = *(const float4*)&sWT[d][4*tx + 64];
        #pragma unroll
        for (int ri = 0; ri < 8; ++ri)
            #pragma unroll
            for (int ci = 0; ci < 8; ++ci)
                acc[ri][ci] += a[ri] * b[ci];
    }
    #pragma unroll
    for (int rs = 0; rs < 8; ++rs) {
        const int r = r0 + ((rs < 4) ? 4*ty + rs : 64 + 4*ty + rs - 4);
        const size_t row = (size_t)r * PSTR;
        const int c0 = p0 + 4*tx;
        if (c0 <= 512)
            *(float4*)(g_P + row + c0) = make_float4(acc[rs][0],acc[rs][1],acc[rs][2],acc[rs][3]);
        const int c1 = p0 + 64 + 4*tx;
        if (c1 <= 512)
            *(float4*)(g_P + row + c1) = make_float4(acc[rs][4],acc[rs][5],acc[rs][6],acc[rs][7]);
    }
}

// ---------------------------------------------------------------------------
// Fused B+C (round-2 structure, 64-row i-blocks, 3 CTA/SM, K-tile prefetch)
// ---------------------------------------------------------------------------
__global__ void __launch_bounds__(256, 3) kernBC(const float* __restrict__ q,
                                                 const float* __restrict__ kmat,
                                                 const float* __restrict__ v,
                                                 float* __restrict__ wbuf,
                                                 float* __restrict__ outp) {
    extern __shared__ float dsm[];
    float (*sQT)[68] = (float(*)[68])(dsm);
    float (*sKT)[68] = (float(*)[68])(dsm + 4352);
    float (*sV)[68]  = (float(*)[68])(dsm + 8704);
    float (*sET)[68] = (float(*)[68])(dsm + 13056);
    float *sMh  = dsm + 17408;   // [16][64] per-tile running max
    float *sM   = dsm + 18432;
    float *sS   = dsm + 18496;
    float *sCs  = dsm + 18560;
    float *sInv = dsm + 18624;
    float *sFac = dsm + 18688;

    const int bh = blockIdx.y;
    const int ib = 15 - (int)blockIdx.x;     // heavy blocks first
    const int i0 = ib * 64;
    const int rowbase = bh * S_LEN + i0;
    const int tid = threadIdx.x;
    const int tx = tid & 15, ty = tid >> 4;
    const int rl = ty << 2, cl = tx << 2;
    const int lane = tid & 31;

    for (int e = tid; e < 1024; e += 256) {
        int r = e >> 4, c4 = (e & 15) << 2;
        float4 vv = *(const float4*)(q + (size_t)(rowbase + r) * 64 + c4);
        sQT[c4+0][r]=vv.x; sQT[c4+1][r]=vv.y; sQT[c4+2][r]=vv.z; sQT[c4+3][r]=vv.w;
    }
    if (tid < 64) { sM[tid] = -1e30f; sS[tid] = 0.f; sCs[tid] = 0.f; }

    float accO[4][4] = {};

    // K-tile register prefetch (4 float4 per thread)
    const int pr = tid >> 4, pc4 = (tid & 15) << 2;    // fixed per-thread slot
    float4 rK[4];
    {
        const size_t base = (size_t)(bh * S_LEN) * 64;
        #pragma unroll
        for (int l = 0; l < 4; ++l)
            rK[l] = *(const float4*)(kmat + base + (size_t)(pr + l*16) * 64 + pc4);
    }

    for (int jb = 0; jb <= ib; ++jb) {
        const int j0 = jb * 64;
        __syncthreads();
        // commit prefetched K tile (transposed) + load V tile
        #pragma unroll
        for (int l = 0; l < 4; ++l) {
            int r = pr + l * 16;
            sKT[pc4+0][r]=rK[l].x; sKT[pc4+1][r]=rK[l].y;
            sKT[pc4+2][r]=rK[l].z; sKT[pc4+3][r]=rK[l].w;
        }
        #pragma unroll
        for (int l = 0; l < 4; ++l) {
            int e = tid + l * 256;
            int r = e >> 4, c4 = (e & 15) << 2;
            *(float4*)&sV[r][c4] = *(const float4*)(v + (size_t)(bh*S_LEN + j0 + r)*64 + c4);
        }
        // issue next K-tile loads early (hidden behind the GEMMs)
        if (jb < ib) {
            const size_t base = (size_t)(bh * S_LEN + j0 + 64) * 64;
            #pragma unroll
            for (int l = 0; l < 4; ++l)
                rK[l] = *(const float4*)(kmat + base + (size_t)(pr + l*16) * 64 + pc4);
        }
        __syncthreads();

        float accQ[4][4] = {};
        #pragma unroll 16
        for (int d = 0; d < 64; ++d) {
            float4 a4 = *(const float4*)&sQT[d][rl];
            float4 b4 = *(const float4*)&sKT[d][cl];
            const float a[4] = {a4.x, a4.y, a4.z, a4.w};
            const float b[4] = {b4.x, b4.y, b4.z, b4.w};
            #pragma unroll
            for (int ri = 0; ri < 4; ++ri)
                #pragma unroll
                for (int ci = 0; ci < 4; ++ci)
                    accQ[ri][ci] += a[ri] * b[ci];
        }

        // relative-key bias + causal mask
        #pragma unroll
        for (int ri = 0; ri < 4; ++ri) {
            const int i = i0 + rl + ri;
            const size_t prow = (size_t)(rowbase + rl + ri) * PSTR;
            #pragma unroll
            for (int ci = 0; ci < 4; ++ci) {
                const int j = j0 + cl + ci;
                int p = j - i + 512; if (p < 0) p = 0;
                accQ[ri][ci] += g_P[prow + p];
                if (j > i) accQ[ri][ci] = -1e30f;
            }
        }

        // online stats + E (one exp per element total)
        float ev[4][4];
        #pragma unroll
        for (int ri = 0; ri < 4; ++ri) {
            const int r = rl + ri;
            float mx = fmaxf(fmaxf(accQ[ri][0], accQ[ri][1]), fmaxf(accQ[ri][2], accQ[ri][3]));
            #pragma unroll
            for (int off = 8; off >= 1; off >>= 1)
                mx = fmaxf(mx, __shfl_xor_sync(0xffffffffu, mx, off));
            const float oldm = sM[r];
            const float newm = fmaxf(oldm, mx);
            float cfr0 = (tx == 0) ? __expf(oldm - newm) : 0.f;
            const float cfr = __shfl_sync(0xffffffffu, cfr0, lane & 16);
            #pragma unroll
            for (int ci = 0; ci < 4; ++ci) ev[ri][ci] = __expf(accQ[ri][ci] - newm);
            float se = ev[ri][0] + ev[ri][1] + ev[ri][2] + ev[ri][3];
            #pragma unroll
            for (int off = 8; off >= 1; off >>= 1)
                se += __shfl_xor_sync(0xffffffffu, se, off);
            if (tx == 0) { sS[r] = sS[r] * cfr + se; sM[r] = newm; sMh[jb * 64 + r] = newm; }
            #pragma unroll
            for (int ci = 0; ci < 4; ++ci) accO[ri][ci] *= cfr;
        }

        // write E to wbuf (raw, rescaled in pass2) + transposed smem for E@V
        #pragma unroll
        for (int ri = 0; ri < 4; ++ri) {
            float4 w = make_float4(ev[ri][0], ev[ri][1], ev[ri][2], ev[ri][3]);
            *(float4*)(wbuf + (size_t)(rowbase + rl + ri) * S_LEN + j0 + cl) = w;
            #pragma unroll
            for (int ci = 0; ci < 4; ++ci) sET[cl + ci][rl + ri] = ev[ri][ci];
        }
        __syncthreads();

        // accO += E @ V
        #pragma unroll 16
        for (int j = 0; j < 64; ++j) {
            float4 a4 = *(const float4*)&sET[j][rl];
            float4 b4 = *(const float4*)&sV[j][cl];
            const float a[4] = {a4.x, a4.y, a4.z, a4.w};
            const float b[4] = {b4.x, b4.y, b4.z, b4.w};
            #pragma unroll
            for (int ri = 0; ri < 4; ++ri)
                #pragma unroll
                for (int ci = 0; ci < 4; ++ci)
                    accO[ri][ci] += a[ri] * b[ci];
        }
    }

    __syncthreads();
    if (tid < 64) sInv[tid] = 1.0f / sS[tid];
    __syncthreads();

    // first-term output (rel-val GEMM added by kernD)
    #pragma unroll
    for (int ri = 0; ri < 4; ++ri) {
        const float inv = sInv[rl + ri];
        float4 o = make_float4(accO[ri][0]*inv, accO[ri][1]*inv, accO[ri][2]*inv, accO[ri][3]*inv);
        *(float4*)(outp + (size_t)(rowbase + rl + ri) * 64 + cl) = o;
    }

    // pass2: finalize weights in wbuf + scatter shifted weights into g_C
    for (int jb = 0; jb < 16; ++jb) {
        const int j0 = jb * 64;
        if (jb > ib) {   // strict upper triangle: exact zeros
            const float4 z = make_float4(0.f, 0.f, 0.f, 0.f);
            for (int e = tid; e < 1024; e += 256) {
                int r = e >> 4, c4 = (e & 15) << 2;
                *(float4*)(wbuf + (size_t)(rowbase + r) * S_LEN + j0 + c4) = z;
            }
            continue;
        }
        __syncthreads();
        if (tid < 64) sFac[tid] = __expf(sMh[jb * 64 + tid] - sM[tid]) * sInv[tid];
        __syncthreads();
        for (int e = tid; e < 1024; e += 256) {
            int r = e >> 4, c4 = (e & 15) << 2;
            size_t addr = (size_t)(rowbase + r) * S_LEN + j0 + c4;
            float4 w = *(float4*)(wbuf + addr);
            const float f = sFac[r];
            w.x *= f; w.y *= f; w.z *= f; w.w *= f;
            *(float4*)(wbuf + addr) = w;
            const int i = i0 + r;
            const size_t crow = (size_t)(rowbase + r) * PSTR;
            const float wv[4] = {w.x, w.y, w.z, w.w};
            #pragma unroll
            for (int t = 0; t < 4; ++t) {
                int mm = i - (j0 + c4 + t);
                if (mm >= 0) {
                    if (mm < 512) g_C[crow + mm] = wv[t];
                    else          atomicAdd(&sCs[r], wv[t]);
                }
            }
        }
    }
    __syncthreads();
    if (tid < 64) g_C[(size_t)(rowbase + tid) * PSTR + 512] = sCs[tid];
    if (i0 < 512) {  // zero-fill never-written slots (m in (i,512))
        for (int idx = tid; idx < 64 * 512; idx += 256) {
            int r = idx >> 9, mm = idx & 511;
            if (mm > i0 + r) g_C[(size_t)(rowbase + r) * PSTR + mm] = 0.f;
        }
    }
}

// ---------------------------------------------------------------------------
// Kernel D: out += C @ Wv_rev, 256x64 tiles, 8x8 accum, K chunks of 64,
// truncated at m <= i0+255 (causal zeros above).
// ---------------------------------------------------------------------------
__global__ void __launch_bounds__(256) kernD(const float* __restrict__ Wv,
                                             float* __restrict__ outp) {
    extern __shared__ float dsmD[];
    float (*sCT)[260] = (float(*)[260])(dsmD);            // [m][r] 64x260
    float (*sB)[68]   = (float(*)[68])(dsmD + 16640);     // [m][d] 64x68
    const int r0 = blockIdx.x * 256;
    const int i0 = r0 & (S_LEN - 1);
    const int mEnd = min(NP, i0 + 256);
    const int tid = threadIdx.x;
    const int tx = tid & 7, ty = tid >> 3;   // tx: 8 col groups, ty: 32 row groups
    float acc[8][8] = {};

    for (int m0 = 0; m0 < mEnd; m0 += 64) {
        __syncthreads();
        #pragma unroll
        for (int l = 0; l < 16; ++l) {
            int e = tid + l * 256;
            int r = e & 255, c4 = (e >> 8) << 2;
            int mb = m0 + c4;
            float4 vv = make_float4(0.f,0.f,0.f,0.f);
            if (mb + 3 <= 512)
                vv = *(const float4*)(g_C + (size_t)(r0 + r)*PSTR + mb);
            else if (mb <= 512)
                vv.x = g_C[(size_t)(r0 + r)*PSTR + 512];
            sCT[c4+0][r]=vv.x; sCT[c4+1][r]=vv.y; sCT[c4+2][r]=vv.z; sCT[c4+3][r]=vv.w;
        }
        #pragma unroll
        for (int l = 0; l < 4; ++l) {
            int e = tid + l * 256;
            int mm = e >> 4, c4 = (e & 15) << 2;
            int m = m0 + mm;
            float4 vv = make_float4(0.f,0.f,0.f,0.f);
            if (m < NP) vv = *(const float4*)(Wv + (size_t)(512 - m)*64 + c4);
            *(float4*)&sB[mm][c4] = vv;
        }
        __syncthreads();
        #pragma unroll 8
        for (int m = 0; m < 64; ++m) {
            float a[8], b[8];
            *(float4*)&a[0] = *(const float4*)&sCT[m][4*ty];
            *(float4*)&a[4] = *(const float4*)&sCT[m][4*ty + 128];
            *(float4*)&b[0] = *(const float4*)&sB[m][4*tx];
            *(float4*)&b[4] = *(const float4*)&sB[m][4*tx + 32];
            #pragma unroll
            for (int ri = 0; ri < 8; ++ri)
                #pragma unroll
                for (int ci = 0; ci < 8; ++ci)
                    acc[ri][ci] += a[ri] * b[ci];
        }
    }
    #pragma unroll
    for (int rs = 0; rs < 8; ++rs) {
        const int r = r0 + ((rs < 4) ? 4*ty + rs : 128 + 4*ty + rs - 4);
        #pragma unroll
        for (int g = 0; g < 2; ++g) {
            size_t a = (size_t)r * 64 + 4*tx + g*32;
            float4 o = *(float4*)(outp + a);
            o.x += acc[rs][g*4+0]; o.y += acc[rs][g*4+1];
            o.z += acc[rs][g*4+2]; o.w += acc[rs][g*4+3];
            *(float4*)(outp + a) = o;
        }
    }
}

// ---------------------------------------------------------------------------
extern "C" void kernel_launch(void* const* d_in, const int* in_sizes, int n_in,
                              void* d_out, int out_size) {
    const float* q  = (const float*)d_in[0];
    const float* k  = (const float*)d_in[1];
    const float* v  = (const float*)d_in[2];
    const float* Wk = (const float*)d_in[3];
    const float* Wv = (const float*)d_in[4];

    float* outp = (float*)d_out;            // (B,H,S,D)
    float* wbuf = outp + OUT_ELEMS;         // (B,H,S,S) weights

    static bool attrs_set = false;
    if (!attrs_set) {
        cudaFuncSetAttribute(kernA,  cudaFuncAttributeMaxDynamicSharedMemorySize, 67584);
        cudaFuncSetAttribute(kernBC, cudaFuncAttributeMaxDynamicSharedMemorySize, 75008);
        cudaFuncSetAttribute(kernD,  cudaFuncAttributeMaxDynamicSharedMemorySize, 83968);
        attrs_set = true;
    }
    kernA<<<dim3(512, 5), 256, 67584>>>(q, Wk);
    kernBC<<<dim3(16, 64), 256, 75008>>>(q, k, v, wbuf, outp);
    kernD<<<dim3(256), 256, 83968>>>(Wv, outp);
}

// round 5
// speedup vs baseline: 1.1770x; 1.0791x over previous
#include <cuda_runtime.h>

#define S_LEN 1024
#define NP 513
#define PSTR 516
#define OUT_ELEMS 4194304
#define NROWS 65536

__device__ float g_P[(size_t)NROWS * PSTR];   // P[row,p] = q[row]·Wk[p]
__device__ float g_C[(size_t)NROWS * PSTR];   // unnormalized shifted weights E
__device__ float g_SInv[NROWS];               // 1/sumexp per row

// ---------------------------------------------------------------------------
// Kernel A: P = Q @ Wk^T, 128x128 tiles, 8x8 accum, full-K resident
// ---------------------------------------------------------------------------
__global__ void __launch_bounds__(256) kernA(const float* __restrict__ q,
                                             const float* __restrict__ Wk) {
    const int r0 = blockIdx.x * 128;
    const int p0 = blockIdx.y * 128;
    const int i0 = r0 & (S_LEN - 1);
    if (p0 + 127 < 385 - i0) return;   // tile entirely below min needed p
    extern __shared__ float dsmA[];
    float (*sQT)[132] = (float(*)[132])(dsmA);          // [d][r]
    float (*sWT)[132] = (float(*)[132])(dsmA + 8448);   // [d][p-p0]
    const int tid = threadIdx.x;
    #pragma unroll
    for (int l = 0; l < 8; ++l) {
        int e = tid + l * 256;
        int r = e & 127, c4 = (e >> 7) << 2;
        float4 vv = *(const float4*)(q + (size_t)(r0 + r) * 64 + c4);
        sQT[c4+0][r]=vv.x; sQT[c4+1][r]=vv.y; sQT[c4+2][r]=vv.z; sQT[c4+3][r]=vv.w;
    }
    #pragma unroll
    for (int l = 0; l < 8; ++l) {
        int e = tid + l * 256;
        int r = e & 127, c4 = (e >> 7) << 2;
        int p = p0 + r;
        float4 vv = make_float4(0.f,0.f,0.f,0.f);
        if (p < NP) vv = *(const float4*)(Wk + (size_t)p * 64 + c4);
        sWT[c4+0][r]=vv.x; sWT[c4+1][r]=vv.y; sWT[c4+2][r]=vv.z; sWT[c4+3][r]=vv.w;
    }
    __syncthreads();
    const int tx = tid & 15, ty = tid >> 4;
    float acc[8][8] = {};
    #pragma unroll 8
    for (int d = 0; d < 64; ++d) {
        float a[8], b[8];
        *(float4*)&a[0] = *(const float4*)&sQT[d][4*ty];
        *(float4*)&a[4] = *(const float4*)&sQT[d][4*ty + 64];
        *(float4*)&b[0] = *(const float4*)&sWT[d][4*tx];
        *(float4*)&b[4] = *(const float4*)&sWT[d][4*tx + 64];
        #pragma unroll
        for (int ri = 0; ri < 8; ++ri)
            #pragma unroll
            for (int ci = 0; ci < 8; ++ci)
                acc[ri][ci] += a[ri] * b[ci];
    }
    #pragma unroll
    for (int rs = 0; rs < 8; ++rs) {
        const int r = r0 + ((rs < 4) ? 4*ty + rs : 64 + 4*ty + rs - 4);
        const size_t row = (size_t)r * PSTR;
        const int c0 = p0 + 4*tx;
        if (c0 <= 512)
            *(float4*)(g_P + row + c0) = make_float4(acc[rs][0],acc[rs][1],acc[rs][2],acc[rs][3]);
        const int c1 = p0 + 64 + 4*tx;
        if (c1 <= 512)
            *(float4*)(g_P + row + c1) = make_float4(acc[rs][4],acc[rs][5],acc[rs][6],acc[rs][7]);
    }
}

// ---------------------------------------------------------------------------
// Fused B+C: no-max softmax. Pass1: logits -> E=exp(l), write E to wbuf,
// scatter E into g_C, accumulate accO = E@V, rowsum s. Pass2: normalize wbuf.
// ---------------------------------------------------------------------------
__global__ void __launch_bounds__(256) kernBC(const float* __restrict__ q,
                                              const float* __restrict__ kmat,
                                              const float* __restrict__ v,
                                              float* __restrict__ wbuf,
                                              float* __restrict__ outp) {
    extern __shared__ float dsm[];
    float (*sQT)[68] = (float(*)[68])(dsm);
    float (*sKT)[68] = (float(*)[68])(dsm + 4352);
    float (*sV)[68]  = (float(*)[68])(dsm + 8704);
    float (*sET)[68] = (float(*)[68])(dsm + 13056);
    float *sS   = dsm + 17408;
    float *sCs  = dsm + 17472;
    float *sInv = dsm + 17536;

    const int bh = blockIdx.y;
    const int ib = 15 - (int)blockIdx.x;     // heavy blocks first
    const int i0 = ib * 64;
    const int rowbase = bh * S_LEN + i0;
    const int tid = threadIdx.x;
    const int tx = tid & 15, ty = tid >> 4;
    const int rl = ty << 2, cl = tx << 2;

    for (int e = tid; e < 1024; e += 256) {
        int r = e >> 4, c4 = (e & 15) << 2;
        float4 vv = *(const float4*)(q + (size_t)(rowbase + r) * 64 + c4);
        sQT[c4+0][r]=vv.x; sQT[c4+1][r]=vv.y; sQT[c4+2][r]=vv.z; sQT[c4+3][r]=vv.w;
    }
    if (tid < 64) { sS[tid] = 0.f; sCs[tid] = 0.f; }

    float accO[4][4] = {};

    for (int jb = 0; jb <= ib; ++jb) {
        const int j0 = jb * 64;
        __syncthreads();
        for (int e = tid; e < 1024; e += 256) {
            int r = e >> 4, c4 = (e & 15) << 2;
            float4 vv = *(const float4*)(kmat + (size_t)(bh*S_LEN + j0 + r)*64 + c4);
            sKT[c4+0][r]=vv.x; sKT[c4+1][r]=vv.y; sKT[c4+2][r]=vv.z; sKT[c4+3][r]=vv.w;
        }
        #pragma unroll
        for (int l = 0; l < 4; ++l) {
            int e = tid + l * 256;
            int r = e >> 4, c4 = (e & 15) << 2;
            *(float4*)&sV[r][c4] = *(const float4*)(v + (size_t)(bh*S_LEN + j0 + r)*64 + c4);
        }
        __syncthreads();

        float accQ[4][4] = {};
        #pragma unroll 16
        for (int d = 0; d < 64; ++d) {
            float4 a4 = *(const float4*)&sQT[d][rl];
            float4 b4 = *(const float4*)&sKT[d][cl];
            const float a[4] = {a4.x, a4.y, a4.z, a4.w};
            const float b[4] = {b4.x, b4.y, b4.z, b4.w};
            #pragma unroll
            for (int ri = 0; ri < 4; ++ri)
                #pragma unroll
                for (int ci = 0; ci < 4; ++ci)
                    accQ[ri][ci] += a[ri] * b[ci];
        }

        // bias + mask + exp + rowsum + scatter
        #pragma unroll
        for (int ri = 0; ri < 4; ++ri) {
            const int r = rl + ri;
            const int i = i0 + r;
            const size_t prow = (size_t)(rowbase + r) * PSTR;
            const size_t crow = prow;   // g_C has same layout
            #pragma unroll
            for (int ci = 0; ci < 4; ++ci) {
                const int j = j0 + cl + ci;
                int p = j - i + 512; if (p < 0) p = 0;
                float l = accQ[ri][ci] + g_P[prow + p];
                if (j > i) l = -1e30f;            // exp -> 0 exactly
                accQ[ri][ci] = __expf(l);
            }
            float se = accQ[ri][0] + accQ[ri][1] + accQ[ri][2] + accQ[ri][3];
            #pragma unroll
            for (int off = 8; off >= 1; off >>= 1)
                se += __shfl_xor_sync(0xffffffffu, se, off);
            if (tx == 0) sS[r] += se;
            // scatter E into g_C (m = i - j)
            #pragma unroll
            for (int ci = 0; ci < 4; ++ci) {
                const int mm = i - (j0 + cl + ci);
                if (mm >= 0) {
                    if (mm < 512) g_C[crow + mm] = accQ[ri][ci];
                    else          atomicAdd(&sCs[r], accQ[ri][ci]);
                }
            }
        }

        // E -> wbuf (raw) + transposed smem for E@V
        #pragma unroll
        for (int ri = 0; ri < 4; ++ri) {
            float4 w = make_float4(accQ[ri][0], accQ[ri][1], accQ[ri][2], accQ[ri][3]);
            *(float4*)(wbuf + (size_t)(rowbase + rl + ri) * S_LEN + j0 + cl) = w;
            #pragma unroll
            for (int ci = 0; ci < 4; ++ci) sET[cl + ci][rl + ri] = accQ[ri][ci];
        }
        __syncthreads();

        // accO += E @ V
        #pragma unroll 16
        for (int j = 0; j < 64; ++j) {
            float4 a4 = *(const float4*)&sET[j][rl];
            float4 b4 = *(const float4*)&sV[j][cl];
            const float a[4] = {a4.x, a4.y, a4.z, a4.w};
            const float b[4] = {b4.x, b4.y, b4.z, b4.w};
            #pragma unroll
            for (int ri = 0; ri < 4; ++ri)
                #pragma unroll
                for (int ci = 0; ci < 4; ++ci)
                    accO[ri][ci] += a[ri] * b[ci];
        }
    }

    __syncthreads();
    if (tid < 64) {
        const float inv = 1.0f / sS[tid];
        sInv[tid] = inv;
        g_SInv[rowbase + tid] = inv;
        g_C[(size_t)(rowbase + tid) * PSTR + 512] = sCs[tid];
    }
    __syncthreads();

    // first-term output (rel-val GEMM added by kernD)
    #pragma unroll
    for (int ri = 0; ri < 4; ++ri) {
        const float inv = sInv[rl + ri];
        float4 o = make_float4(accO[ri][0]*inv, accO[ri][1]*inv, accO[ri][2]*inv, accO[ri][3]*inv);
        *(float4*)(outp + (size_t)(rowbase + rl + ri) * 64 + cl) = o;
    }

    // pass2: normalize wbuf (pure streaming) + zero upper triangle
    for (int jb = 0; jb < 16; ++jb) {
        const int j0 = jb * 64;
        if (jb > ib) {
            const float4 z = make_float4(0.f, 0.f, 0.f, 0.f);
            for (int e = tid; e < 1024; e += 256) {
                int r = e >> 4, c4 = (e & 15) << 2;
                *(float4*)(wbuf + (size_t)(rowbase + r) * S_LEN + j0 + c4) = z;
            }
            continue;
        }
        for (int e = tid; e < 1024; e += 256) {
            int r = e >> 4, c4 = (e & 15) << 2;
            size_t addr = (size_t)(rowbase + r) * S_LEN + j0 + c4;
            float4 w = *(float4*)(wbuf + addr);
            const float f = sInv[r];
            w.x *= f; w.y *= f; w.z *= f; w.w *= f;
            *(float4*)(wbuf + addr) = w;
        }
    }

    if (i0 < 512) {  // zero-fill never-written g_C slots (m in (i,512))
        for (int idx = tid; idx < 64 * 512; idx += 256) {
            int r = idx >> 9, mm = idx & 511;
            if (mm > i0 + r) g_C[(size_t)(rowbase + r) * PSTR + mm] = 0.f;
        }
    }
}

// ---------------------------------------------------------------------------
// Kernel D: out += sInv[r] * (C_E @ Wv_rev), 256x64 tiles, 8x8 accum,
// K chunks of 64, truncated at m <= i0+255 (causal zeros above).
// ---------------------------------------------------------------------------
__global__ void __launch_bounds__(256) kernD(const float* __restrict__ Wv,
                                             float* __restrict__ outp) {
    extern __shared__ float dsmD[];
    float (*sCT)[260] = (float(*)[260])(dsmD);            // [m][r] 64x260
    float (*sB)[68]   = (float(*)[68])(dsmD + 16640);     // [m][d] 64x68
    const int r0 = blockIdx.x * 256;
    const int i0 = r0 & (S_LEN - 1);
    const int mEnd = min(NP, i0 + 256);
    const int tid = threadIdx.x;
    const int tx = tid & 7, ty = tid >> 3;   // tx: 8 col groups, ty: 32 row groups
    float acc[8][8] = {};

    for (int m0 = 0; m0 < mEnd; m0 += 64) {
        __syncthreads();
        #pragma unroll
        for (int l = 0; l < 16; ++l) {
            int e = tid + l * 256;
            int r = e & 255, c4 = (e >> 8) << 2;
            int mb = m0 + c4;
            float4 vv = make_float4(0.f,0.f,0.f,0.f);
            if (mb + 3 <= 512)
                vv = *(const float4*)(g_C + (size_t)(r0 + r)*PSTR + mb);
            else if (mb <= 512)
                vv.x = g_C[(size_t)(r0 + r)*PSTR + 512];
            sCT[c4+0][r]=vv.x; sCT[c4+1][r]=vv.y; sCT[c4+2][r]=vv.z; sCT[c4+3][r]=vv.w;
        }
        #pragma unroll
        for (int l = 0; l < 4; ++l) {
            int e = tid + l * 256;
            int mm = e >> 4, c4 = (e & 15) << 2;
            int m = m0 + mm;
            float4 vv = make_float4(0.f,0.f,0.f,0.f);
            if (m < NP) vv = *(const float4*)(Wv + (size_t)(512 - m)*64 + c4);
            *(float4*)&sB[mm][c4] = vv;
        }
        __syncthreads();
        #pragma unroll 8
        for (int m = 0; m < 64; ++m) {
            float a[8], b[8];
            *(float4*)&a[0] = *(const float4*)&sCT[m][4*ty];
            *(float4*)&a[4] = *(const float4*)&sCT[m][4*ty + 128];
            *(float4*)&b[0] = *(const float4*)&sB[m][4*tx];
            *(float4*)&b[4] = *(const float4*)&sB[m][4*tx + 32];
            #pragma unroll
            for (int ri = 0; ri < 8; ++ri)
                #pragma unroll
                for (int ci = 0; ci < 8; ++ci)
                    acc[ri][ci] += a[ri] * b[ci];
        }
    }
    #pragma unroll
    for (int rs = 0; rs < 8; ++rs) {
        const int r = r0 + ((rs < 4) ? 4*ty + rs : 128 + 4*ty + rs - 4);
        const float sinv = g_SInv[r];
        #pragma unroll
        for (int g = 0; g < 2; ++g) {
            size_t a = (size_t)r * 64 + 4*tx + g*32;
            float4 o = *(float4*)(outp + a);
            o.x += acc[rs][g*4+0]*sinv; o.y += acc[rs][g*4+1]*sinv;
            o.z += acc[rs][g*4+2]*sinv; o.w += acc[rs][g*4+3]*sinv;
            *(float4*)(outp + a) = o;
        }
    }
}

// ---------------------------------------------------------------------------
extern "C" void kernel_launch(void* const* d_in, const int* in_sizes, int n_in,
                              void* d_out, int out_size) {
    const float* q  = (const float*)d_in[0];
    const float* k  = (const float*)d_in[1];
    const float* v  = (const float*)d_in[2];
    const float* Wk = (const float*)d_in[3];
    const float* Wv = (const float*)d_in[4];

    float* outp = (float*)d_out;            // (B,H,S,D)
    float* wbuf = outp + OUT_ELEMS;         // (B,H,S,S) weights

    static bool attrs_set = false;
    if (!attrs_set) {
        cudaFuncSetAttribute(kernA,  cudaFuncAttributeMaxDynamicSharedMemorySize, 67584);
        cudaFuncSetAttribute(kernBC, cudaFuncAttributeMaxDynamicSharedMemorySize, 70400);
        cudaFuncSetAttribute(kernD,  cudaFuncAttributeMaxDynamicSharedMemorySize, 83968);
        attrs_set = true;
    }
    kernA<<<dim3(512, 5), 256, 67584>>>(q, Wk);
    kernBC<<<dim3(16, 64), 256, 70400>>>(q, k, v, wbuf, outp);
    kernD<<<dim3(256), 256, 83968>>>(Wv, outp);
}